// round 1
// baseline (speedup 1.0000x reference)
#include <cuda_runtime.h>
#include <math.h>

// Problem constants (fixed by the dataset).
#define E_CONST 64
#define H_CONST 512
#define F_CONST 2048
#define T_CONST 2048

// Scratch: per-expert prefix offsets + the intermediate activation h = gelu(x @ w1^T).
__device__ int g_offs[E_CONST + 1];
__device__ float g_hbuf[(size_t)T_CONST * F_CONST];  // 16 MB, [T, F]

// ---------------------------------------------------------------------------
// Tiny scan: offsets into the token-sorted x.
// ---------------------------------------------------------------------------
__global__ void scan_kernel(const int* __restrict__ counts) {
    if (threadIdx.x == 0) {
        int s = 0;
        for (int e = 0; e < E_CONST; ++e) { g_offs[e] = s; s += counts[e]; }
        g_offs[E_CONST] = s;
    }
}

__device__ __forceinline__ float gelu_exact(float v) {
    return 0.5f * v * (1.0f + erff(v * 0.70710678118654752f));
}

// ---------------------------------------------------------------------------
// Phase 1: g_hbuf[t, f] = gelu( sum_k x[t, k] * w1[e, f, k] )
// grid: (F/128, E), block: 256 threads.
// Block tile: 128 f  x  32 tokens, K-chunks of 32.
// Thread tile: 8 f x 2 t. Weight frags are warp-broadcast LDS (2 distinct
// addrs/warp); token frags are one aligned LDS.64.
// ---------------------------------------------------------------------------
__global__ __launch_bounds__(256) void phase1_kernel(
    const float* __restrict__ x, const float* __restrict__ w1) {
    constexpr int BM = 128, BT = 32, BK = 32;
    __shared__ float wsT[BK][BM + 1];  // [k][f], stride 129 -> conflict-free stores
    __shared__ float xsT[BK][BT + 2];  // [k][t], stride 34 -> 8B-aligned float2 rows

    const int e     = blockIdx.y;
    const int fbase = blockIdx.x * BM;
    const int toff  = g_offs[e];
    const int cnt   = g_offs[e + 1] - toff;
    const int tid   = threadIdx.x;
    const int ty    = tid / 16;   // 16 groups x 8 f
    const int tx    = tid % 16;   // 16 groups x 2 t
    const float* w1e = w1 + (size_t)e * F_CONST * H_CONST;

    for (int tbase = 0; tbase < cnt; tbase += BT) {
        float acc[8][2];
        #pragma unroll
        for (int i = 0; i < 8; ++i) { acc[i][0] = 0.f; acc[i][1] = 0.f; }

        for (int k0 = 0; k0 < H_CONST; k0 += BK) {
            // Load weight tile 128x32 (k fastest -> coalesced 128B per warp).
            #pragma unroll
            for (int i = 0; i < (BM * BK) / 256; ++i) {
                int idx = tid + i * 256;
                int k = idx % BK, f = idx / BK;
                wsT[k][f] = w1e[(size_t)(fbase + f) * H_CONST + (k0 + k)];
            }
            // Load token tile 32x32, zero-padded past cnt.
            #pragma unroll
            for (int i = 0; i < (BT * BK) / 256; ++i) {
                int idx = tid + i * 256;
                int k = idx % BK, t = idx / BK;
                float v = 0.f;
                if (tbase + t < cnt)
                    v = x[(size_t)(toff + tbase + t) * H_CONST + (k0 + k)];
                xsT[k][t] = v;
            }
            __syncthreads();
            #pragma unroll
            for (int k = 0; k < BK; ++k) {
                float2 xv = *reinterpret_cast<const float2*>(&xsT[k][tx * 2]);
                #pragma unroll
                for (int i = 0; i < 8; ++i) {
                    float wv = wsT[k][ty * 8 + i];
                    acc[i][0] = fmaf(wv, xv.x, acc[i][0]);
                    acc[i][1] = fmaf(wv, xv.y, acc[i][1]);
                }
            }
            __syncthreads();
        }
        #pragma unroll
        for (int j = 0; j < 2; ++j) {
            int t = tbase + tx * 2 + j;
            if (t < cnt) {
                float* dst = g_hbuf + (size_t)(toff + t) * F_CONST + fbase;
                #pragma unroll
                for (int i = 0; i < 8; ++i)
                    dst[ty * 8 + i] = gelu_exact(acc[i][j]);
            }
        }
    }
}

// ---------------------------------------------------------------------------
// Phase 2: out[t, h] = sum_f g_hbuf[t, f] * w2[e, f, h]
// grid: (H/64, E), block: 256 threads.
// Block tile: 64 h x 32 tokens, K-chunks of 32 over F=2048.
// Thread tile: 4 h x 2 t.
// ---------------------------------------------------------------------------
__global__ __launch_bounds__(256) void phase2_kernel(
    const float* __restrict__ w2, float* __restrict__ out) {
    constexpr int BN = 64, BT = 32, BK = 32;
    __shared__ float ws[BK][BN + 1];   // [k][h]
    __shared__ float hs[BK][BT + 2];   // [k][t]

    const int e     = blockIdx.y;
    const int hbase = blockIdx.x * BN;
    const int toff  = g_offs[e];
    const int cnt   = g_offs[e + 1] - toff;
    const int tid   = threadIdx.x;
    const int hy    = tid / 16;   // 16 groups x 4 h
    const int tx    = tid % 16;   // 16 groups x 2 t
    const float* w2e = w2 + (size_t)e * F_CONST * H_CONST;

    for (int tbase = 0; tbase < cnt; tbase += BT) {
        float acc[4][2];
        #pragma unroll
        for (int i = 0; i < 4; ++i) { acc[i][0] = 0.f; acc[i][1] = 0.f; }

        for (int k0 = 0; k0 < F_CONST; k0 += BK) {
            // w2 tile 32x64 (h fastest in gmem -> coalesced, conflict-free STS).
            #pragma unroll
            for (int i = 0; i < (BK * BN) / 256; ++i) {
                int idx = tid + i * 256;
                int h = idx % BN, k = idx / BN;
                ws[k][h] = w2e[(size_t)(k0 + k) * H_CONST + (hbase + h)];
            }
            // h tile 32x32 from scratch (f fastest -> coalesced).
            #pragma unroll
            for (int i = 0; i < (BT * BK) / 256; ++i) {
                int idx = tid + i * 256;
                int k = idx % BK, t = idx / BK;
                float v = 0.f;
                if (tbase + t < cnt)
                    v = g_hbuf[(size_t)(toff + tbase + t) * F_CONST + (k0 + k)];
                hs[k][t] = v;
            }
            __syncthreads();
            #pragma unroll
            for (int k = 0; k < BK; ++k) {
                float2 hv = *reinterpret_cast<const float2*>(&hs[k][tx * 2]);
                #pragma unroll
                for (int i = 0; i < 4; ++i) {
                    float wv = ws[k][hy * 4 + i];
                    acc[i][0] = fmaf(wv, hv.x, acc[i][0]);
                    acc[i][1] = fmaf(wv, hv.y, acc[i][1]);
                }
            }
            __syncthreads();
        }
        #pragma unroll
        for (int j = 0; j < 2; ++j) {
            int t = tbase + tx * 2 + j;
            if (t < cnt) {
                float* dst = out + (size_t)(toff + t) * H_CONST + hbase;
                #pragma unroll
                for (int i = 0; i < 4; ++i)
                    dst[hy * 4 + i] = acc[i][j];
            }
        }
    }
}

// ---------------------------------------------------------------------------
// kernel_launch: inputs per metadata order:
//   d_in[0] = x   [T, H]  f32
//   d_in[1] = w1  [E, F, H] f32
//   d_in[2] = w2  [E, F, H] f32
//   d_in[3] = tokens_per_expert [E] i32
// d_out = [T, H] f32
// ---------------------------------------------------------------------------
extern "C" void kernel_launch(void* const* d_in, const int* in_sizes, int n_in,
                              void* d_out, int out_size) {
    const float* x      = (const float*)d_in[0];
    const float* w1     = (const float*)d_in[1];
    const float* w2     = (const float*)d_in[2];
    const int*   counts = (const int*)d_in[3];
    float* out = (float*)d_out;

    scan_kernel<<<1, 32>>>(counts);
    phase1_kernel<<<dim3(F_CONST / 128, E_CONST), 256>>>(x, w1);
    phase2_kernel<<<dim3(H_CONST / 64, E_CONST), 256>>>(w2, out);
}

// round 3
// speedup vs baseline: 2.4066x; 2.4066x over previous
#include <cuda_runtime.h>
#include <math.h>
#include <stdint.h>

#define E_N 64
#define H_N 512
#define F_N 2048
#define HB_STRIDE 3072   // padded token columns across all experts (<= 2048 + 64*15)

// Scratch (device globals are zero-initialized at module load).
__device__ int g_offs[E_N + 1];    // real token prefix
__device__ int g_poffs[E_N + 1];   // 16-aligned prefix for hbufT columns
__device__ float g_hbufT[(size_t)F_N * HB_STRIDE];  // [f][padded token], 24 MB

__global__ void scan_kernel(const int* __restrict__ counts) {
    if (threadIdx.x == 0) {
        int s = 0, p = 0;
        for (int e = 0; e < E_N; ++e) {
            g_offs[e] = s; g_poffs[e] = p;
            s += counts[e];
            p += (counts[e] + 15) & ~15;
        }
        g_offs[E_N] = s; g_poffs[E_N] = p;
    }
}

__device__ __forceinline__ uint32_t to_tf32(float f) {
    uint32_t u;
    asm("cvt.rna.tf32.f32 %0, %1;" : "=r"(u) : "f"(f));
    return u;
}
__device__ __forceinline__ float tf32f(float f) {
    return __uint_as_float(to_tf32(f));
}
__device__ __forceinline__ float gelu_exact(float v) {
    return 0.5f * v * (1.0f + erff(v * 0.70710678118654752f));
}
__device__ __forceinline__ void mma8(float c[4], const uint32_t a[4],
                                     uint32_t b0, uint32_t b1) {
    asm volatile(
        "mma.sync.aligned.m16n8k8.row.col.f32.tf32.tf32.f32 "
        "{%0,%1,%2,%3},{%4,%5,%6,%7},{%8,%9},{%0,%1,%2,%3};"
        : "+f"(c[0]), "+f"(c[1]), "+f"(c[2]), "+f"(c[3])
        : "r"(a[0]), "r"(a[1]), "r"(a[2]), "r"(a[3]), "r"(b0), "r"(b1));
}

// ---------------------------------------------------------------------------
// Fragment-pair SMEM layout: per (m-block 16 x k-step 8):
//   element (row, k) at offset row*8 + (k&3)*2 + (k>>2)
// so a thread's (k=tg, k=tg+4) fragment pair is one aligned LDS.64 at 2*lane.
// Block array: [mb][kb][130] (A, 16 rows) / [nb][kb][66] (B, 8 rows);
// even block strides keep LDS.64 aligned, the pad spreads STS banks.
//
// PHASE 1: D[f(256), t(48)] = w1-tile (K-major direct) x x-tile, K=512.
//          epilogue: gelu -> g_hbufT[f][poff+t]   (float2, coalesced)
// PHASE 2: D[h(128), t(48)] = w2-tile (transposed on STS) x hbufT-tile, K=2048.
//          epilogue: out[t][h]                    (32B-sector friendly)
// ---------------------------------------------------------------------------
template <int PHASE>
__global__ void __launch_bounds__(PHASE == 1 ? 256 : 128)
mlp_kernel(const float* __restrict__ x, const float* __restrict__ wgt,
           float* __restrict__ outp) {
    constexpr int BM      = (PHASE == 1) ? 256 : 128;
    constexpr int THREADS = BM;                 // 32 threads per 32 m-rows
    constexpr int NW      = THREADS / 32;
    constexpr int KTOT    = (PHASE == 1) ? H_N : F_N;
    constexpr int NCH     = KTOT / 16;          // BK = 16 (2 k-steps of 8)
    constexpr int MB      = BM / 16;

    __shared__ float As[2][MB * 2 * 130];
    __shared__ float Bs[2][6 * 2 * 66];

    const int tid  = threadIdx.x;
    const int w    = tid >> 5, lane = tid & 31;
    const int g    = lane >> 2, tg = lane & 3;
    const int e     = blockIdx.y;
    const int mbase = blockIdx.x * BM;
    const int toff  = g_offs[e];
    const int cnt   = g_offs[e + 1] - toff;
    const int poff  = g_poffs[e];
    const float* we = wgt + (size_t)e * F_N * H_N;

    float4 rA[4];
    float4 rB[2];

    for (int tbase = 0; tbase < cnt; tbase += 48) {
        // ---------------- stage loaders (gmem -> regs) ----------------
        auto ldA = [&](int c) {
            const int k0 = c * 16;
            #pragma unroll
            for (int i = 0; i < 4; ++i) {
                int q = tid + i * THREADS;
                if (PHASE == 1) {
                    int m = q >> 2, k4 = q & 3;   // float4 along k
                    rA[i] = *(const float4*)&we[(size_t)(mbase + m) * H_N + k0 + k4 * 4];
                } else {
                    int m4 = q & 31, k = q >> 5;  // float4 along m (h contiguous)
                    rA[i] = *(const float4*)&we[(size_t)(k0 + k) * H_N + mbase + m4 * 4];
                }
            }
        };
        auto ldB = [&](int c) {
            const int k0 = c * 16;
            #pragma unroll
            for (int i = 0; i < 2; ++i) {
                int q = tid + i * THREADS;
                if (q < 192) {
                    if (PHASE == 1) {
                        int t = q >> 2, k4 = q & 3;
                        if (tbase + t < cnt)
                            rB[i] = *(const float4*)&x[(size_t)(toff + tbase + t) * H_N + k0 + k4 * 4];
                        else
                            rB[i] = make_float4(0.f, 0.f, 0.f, 0.f);
                    } else {
                        int n4 = q % 12, k = q / 12;
                        // padded region is zero / stale-but-discarded; no guard needed
                        rB[i] = *(const float4*)&g_hbufT[(size_t)(k0 + k) * HB_STRIDE +
                                                         poff + tbase + n4 * 4];
                    }
                }
            }
        };
        // ---------------- stage stores (regs -> smem, cvt.rna) ----------------
        auto stsA = [&](int buf) {
            #pragma unroll
            for (int i = 0; i < 4; ++i) {
                int q = tid + i * THREADS;
                float v[4] = {rA[i].x, rA[i].y, rA[i].z, rA[i].w};
                if (PHASE == 1) {
                    int m = q >> 2, k4 = q & 3;
                    int kb = k4 >> 1, half = k4 & 1;
                    float* blk = &As[buf][((m >> 4) * 2 + kb) * 130];
                    #pragma unroll
                    for (int j = 0; j < 4; ++j)
                        blk[(m & 15) * 8 + j * 2 + half] = tf32f(v[j]);
                } else {
                    int m4 = q & 31, k = q >> 5;
                    int kb = k >> 3, koff = k & 7;
                    int m = m4 * 4;
                    int offk = (koff & 3) * 2 + (koff >> 2);
                    float* blk = &As[buf][((m >> 4) * 2 + kb) * 130];
                    #pragma unroll
                    for (int j = 0; j < 4; ++j)
                        blk[((m + j) & 15) * 8 + offk] = tf32f(v[j]);
                }
            }
        };
        auto stsB = [&](int buf) {
            #pragma unroll
            for (int i = 0; i < 2; ++i) {
                int q = tid + i * THREADS;
                if (q < 192) {
                    float v[4] = {rB[i].x, rB[i].y, rB[i].z, rB[i].w};
                    if (PHASE == 1) {
                        int t = q >> 2, k4 = q & 3;
                        int kb = k4 >> 1, half = k4 & 1;
                        float* blk = &Bs[buf][((t >> 3) * 2 + kb) * 66];
                        #pragma unroll
                        for (int j = 0; j < 4; ++j)
                            blk[(t & 7) * 8 + j * 2 + half] = tf32f(v[j]);
                    } else {
                        int n4 = q % 12, k = q / 12;
                        int kb = k >> 3, koff = k & 7;
                        int n = n4 * 4;
                        int offk = (koff & 3) * 2 + (koff >> 2);
                        float* blk = &Bs[buf][((n >> 3) * 2 + kb) * 66];
                        #pragma unroll
                        for (int j = 0; j < 4; ++j)
                            blk[((n + j) & 7) * 8 + offk] = tf32f(v[j]);
                    }
                }
            }
        };

        // ---------------- accumulators ----------------
        float acc[2][6][4];
        #pragma unroll
        for (int ml = 0; ml < 2; ++ml)
            #pragma unroll
            for (int nb = 0; nb < 6; ++nb)
                #pragma unroll
                for (int r = 0; r < 4; ++r) acc[ml][nb][r] = 0.f;

        // ---------------- pipeline ----------------
        ldA(0); ldB(0);
        stsA(0); stsB(0);
        ldA(1); ldB(1);
        __syncthreads();

        for (int c = 0; c < NCH; ++c) {
            const int buf = c & 1;
            #pragma unroll
            for (int kb = 0; kb < 2; ++kb) {
                uint32_t a[2][4];
                #pragma unroll
                for (int ml = 0; ml < 2; ++ml) {
                    const float* blk = &As[buf][((w * 2 + ml) * 2 + kb) * 130];
                    float2 p0 = *(const float2*)&blk[2 * lane];        // (a0, a2)
                    float2 p1 = *(const float2*)&blk[2 * lane + 64];   // (a1, a3)
                    a[ml][0] = __float_as_uint(p0.x);
                    a[ml][1] = __float_as_uint(p1.x);
                    a[ml][2] = __float_as_uint(p0.y);
                    a[ml][3] = __float_as_uint(p1.y);
                }
                #pragma unroll
                for (int nb = 0; nb < 6; ++nb) {
                    const float* bb = &Bs[buf][(nb * 2 + kb) * 66];
                    float2 pb = *(const float2*)&bb[2 * lane];         // (b0, b1)
                    uint32_t b0 = __float_as_uint(pb.x);
                    uint32_t b1 = __float_as_uint(pb.y);
                    mma8(acc[0][nb], a[0], b0, b1);
                    mma8(acc[1][nb], a[1], b0, b1);
                }
            }
            __syncthreads();
            if (c + 1 < NCH) {
                stsA((c + 1) & 1); stsB((c + 1) & 1);
                if (c + 2 < NCH) { ldA(c + 2); ldB(c + 2); }
                __syncthreads();
            }
        }

        // ---------------- epilogue ----------------
        int nlim = cnt - tbase; if (nlim > 48) nlim = 48;
        #pragma unroll
        for (int ml = 0; ml < 2; ++ml) {
            const int r0 = mbase + (w * 2 + ml) * 16 + g;
            const int r1 = r0 + 8;
            #pragma unroll
            for (int nb = 0; nb < 6; ++nb) {
                const int n0 = nb * 8 + tg * 2;
                const float* c4 = acc[ml][nb];
                if (PHASE == 1) {
                    size_t b0 = (size_t)r0 * HB_STRIDE + poff + tbase + n0;
                    size_t b1 = (size_t)r1 * HB_STRIDE + poff + tbase + n0;
                    if (n0 + 1 < nlim) {
                        *(float2*)&g_hbufT[b0] = make_float2(gelu_exact(c4[0]), gelu_exact(c4[1]));
                        *(float2*)&g_hbufT[b1] = make_float2(gelu_exact(c4[2]), gelu_exact(c4[3]));
                    } else if (n0 < nlim) {
                        g_hbufT[b0] = gelu_exact(c4[0]);
                        g_hbufT[b1] = gelu_exact(c4[2]);
                    }
                } else {
                    const int t0 = toff + tbase + n0;
                    if (n0 < nlim) {
                        outp[(size_t)t0 * H_N + r0] = c4[0];
                        outp[(size_t)t0 * H_N + r1] = c4[2];
                    }
                    if (n0 + 1 < nlim) {
                        outp[(size_t)(t0 + 1) * H_N + r0] = c4[1];
                        outp[(size_t)(t0 + 1) * H_N + r1] = c4[3];
                    }
                }
            }
        }
        __syncthreads();  // smem reuse across token tiles
    }
}

// ---------------------------------------------------------------------------
// Inputs: d_in[0]=x [T,H] f32, d_in[1]=w1 [E,F,H] f32, d_in[2]=w2 [E,F,H] f32,
//         d_in[3]=tokens_per_expert [E] i32.  d_out=[T,H] f32.
// ---------------------------------------------------------------------------
extern "C" void kernel_launch(void* const* d_in, const int* in_sizes, int n_in,
                              void* d_out, int out_size) {
    const float* x      = (const float*)d_in[0];
    const float* w1     = (const float*)d_in[1];
    const float* w2     = (const float*)d_in[2];
    const int*   counts = (const int*)d_in[3];
    float* out = (float*)d_out;

    scan_kernel<<<1, 32>>>(counts);
    mlp_kernel<1><<<dim3(F_N / 256, E_N), 256>>>(x, w1, nullptr);
    mlp_kernel<2><<<dim3(H_N / 128, E_N), 128>>>(x, w2, out);
}

// round 4
// speedup vs baseline: 3.4150x; 1.4190x over previous
#include <cuda_runtime.h>
#include <math.h>
#include <stdint.h>

#define E_N 64
#define H_N 512
#define F_N 2048
#define HB_STRIDE 3072   // padded token columns across all experts (2048 + 64*15 + slack)

// Scratch (device globals; zero-initialized at module load).
__device__ int g_offs[E_N + 1];    // real token prefix
__device__ int g_poffs[E_N + 1];   // 16-aligned prefix for hbufT columns
__device__ float g_hbufT[(size_t)F_N * HB_STRIDE];  // [f][padded token], 24 MB

__global__ void scan_kernel(const int* __restrict__ counts) {
    if (threadIdx.x == 0) {
        int s = 0, p = 0;
        for (int e = 0; e < E_N; ++e) {
            g_offs[e] = s; g_poffs[e] = p;
            s += counts[e];
            p += (counts[e] + 15) & ~15;
        }
        g_offs[E_N] = s; g_poffs[E_N] = p;
    }
}

__device__ __forceinline__ float tf32f(float f) {
    uint32_t u;
    asm("cvt.rna.tf32.f32 %0, %1;" : "=r"(u) : "f"(f));
    return __uint_as_float(u);
}
__device__ __forceinline__ float gelu_exact(float v) {
    return 0.5f * v * (1.0f + erff(v * 0.70710678118654752f));
}
__device__ __forceinline__ void mma8(float c[4], const uint32_t a[4],
                                     uint32_t b0, uint32_t b1) {
    asm volatile(
        "mma.sync.aligned.m16n8k8.row.col.f32.tf32.tf32.f32 "
        "{%0,%1,%2,%3},{%4,%5,%6,%7},{%8,%9},{%0,%1,%2,%3};"
        : "+f"(c[0]), "+f"(c[1]), "+f"(c[2]), "+f"(c[3])
        : "r"(a[0]), "r"(a[1]), "r"(a[2]), "r"(a[3]), "r"(b0), "r"(b1));
}

// ---------------------------------------------------------------------------
// Fragment-pair SMEM layout per (16-row m-block x 8-k step):
//   element (row, k) at row*8 + (k&3)*2 + (k>>2)
// -> a thread's (k, k+4) fragment pair is one aligned LDS.64 at 2*lane.
// Buffers: As[3][8 mb][4 kb][130], Bs[3][6 nb][4 kb][66]  (BK = 32).
//
// Schedule (one barrier per chunk, triple buffer):
//   prime: LDG(0); STS(0); LDG(1); bar;
//   iter c: STS(c+1); LDG(c+2); MMA(c); bar;
//
// PHASE 1: D[f(128), t(48)] = w1-tile (K-major direct) x x-tile, K=512.
//          epilogue: gelu -> g_hbufT[f][poff+t]  (float2-coalesced)
// PHASE 2: D[h(128), t(48)] = w2-tile (transposed on STS) x hbufT-tile, K=2048.
//          epilogue: out[t][h]
// ---------------------------------------------------------------------------
#define ASZ (8 * 4 * 130)   // floats per A stage (4160)
#define BSZ (6 * 4 * 66)    // floats per B stage (1584)
#define STAGE (ASZ + BSZ)   // 5744 floats = 22976 B
#define SMEM_BYTES (3 * STAGE * 4)

template <int PHASE>
__global__ void __launch_bounds__(128)
mlp_kernel(const float* __restrict__ x, const float* __restrict__ wgt,
           float* __restrict__ outp) {
    constexpr int KTOT = (PHASE == 1) ? H_N : F_N;
    constexpr int NCH  = KTOT / 32;

    extern __shared__ float smem[];

    const int tid  = threadIdx.x;
    const int w    = tid >> 5, lane = tid & 31;
    const int g    = lane >> 2, tg = lane & 3;
    const int e     = blockIdx.y;
    const int mbase = blockIdx.x * 128;
    const int toff  = g_offs[e];
    const int cnt   = g_offs[e + 1] - toff;
    const int poff  = g_poffs[e];
    const float* we = wgt + (size_t)e * F_N * H_N;

    float4 rA[8];
    float4 rB[3];

    for (int tbase = 0; tbase < cnt; tbase += 48) {
        // -------- loaders: gmem -> regs (chunk c covers k [32c, 32c+32)) ----
        auto ldA = [&](int c) {
            const int k0 = c * 32;
            #pragma unroll
            for (int i = 0; i < 8; ++i) {
                int q = tid + i * 128;
                if (PHASE == 1) {
                    int m = q >> 3, k4 = q & 7;   // float4 along k
                    rA[i] = *(const float4*)&we[(size_t)(mbase + m) * H_N + k0 + k4 * 4];
                } else {
                    int m4 = q & 31, k = q >> 5;  // float4 along m (h contiguous)
                    rA[i] = *(const float4*)&we[(size_t)(k0 + k) * H_N + mbase + m4 * 4];
                }
            }
        };
        auto ldB = [&](int c) {
            const int k0 = c * 32;
            #pragma unroll
            for (int i = 0; i < 3; ++i) {
                int q = tid + i * 128;            // q < 384
                if (PHASE == 1) {
                    int t = q >> 3, k4 = q & 7;
                    if (tbase + t < cnt)
                        rB[i] = *(const float4*)&x[(size_t)(toff + tbase + t) * H_N + k0 + k4 * 4];
                    else
                        rB[i] = make_float4(0.f, 0.f, 0.f, 0.f);
                } else {
                    int n4 = q % 12, k = q / 12;
                    // over-read into padded/next-expert cols: products discarded in epilogue
                    rB[i] = *(const float4*)&g_hbufT[(size_t)(k0 + k) * HB_STRIDE +
                                                     poff + tbase + n4 * 4];
                }
            }
        };
        // -------- stores: regs -> packed smem (cvt.rna on the way) ----------
        auto stsA = [&](float* As) {
            #pragma unroll
            for (int i = 0; i < 8; ++i) {
                int q = tid + i * 128;
                float v[4] = {rA[i].x, rA[i].y, rA[i].z, rA[i].w};
                if (PHASE == 1) {
                    int m = q >> 3, k4 = q & 7;
                    int kb = k4 >> 1, half = k4 & 1;
                    float* blk = &As[((m >> 4) * 4 + kb) * 130];
                    #pragma unroll
                    for (int j = 0; j < 4; ++j)
                        blk[(m & 15) * 8 + j * 2 + half] = tf32f(v[j]);
                } else {
                    int m4 = q & 31, k = q >> 5;
                    int kb = k >> 3, koff = k & 7;
                    int m = m4 * 4;
                    int offk = (koff & 3) * 2 + (koff >> 2);
                    float* blk = &As[((m >> 4) * 4 + kb) * 130];
                    #pragma unroll
                    for (int j = 0; j < 4; ++j)
                        blk[((m + j) & 15) * 8 + offk] = tf32f(v[j]);
                }
            }
        };
        auto stsB = [&](float* Bs) {
            #pragma unroll
            for (int i = 0; i < 3; ++i) {
                int q = tid + i * 128;
                float v[4] = {rB[i].x, rB[i].y, rB[i].z, rB[i].w};
                if (PHASE == 1) {
                    int t = q >> 3, k4 = q & 7;
                    int kb = k4 >> 1, half = k4 & 1;
                    float* blk = &Bs[((t >> 3) * 4 + kb) * 66];
                    #pragma unroll
                    for (int j = 0; j < 4; ++j)
                        blk[(t & 7) * 8 + j * 2 + half] = tf32f(v[j]);
                } else {
                    int n4 = q % 12, k = q / 12;
                    int kb = k >> 3, koff = k & 7;
                    int n = n4 * 4;
                    int offk = (koff & 3) * 2 + (koff >> 2);
                    float* blk = &Bs[((n >> 3) * 4 + kb) * 66];
                    #pragma unroll
                    for (int j = 0; j < 4; ++j)
                        blk[((n + j) & 7) * 8 + offk] = tf32f(v[j]);
                }
            }
        };

        float acc[2][6][4];
        #pragma unroll
        for (int ml = 0; ml < 2; ++ml)
            #pragma unroll
            for (int nb = 0; nb < 6; ++nb)
                #pragma unroll
                for (int r = 0; r < 4; ++r) acc[ml][nb][r] = 0.f;

        // -------- prime --------
        ldA(0); ldB(0);
        stsA(smem); stsB(smem + ASZ);
        ldA(1); ldB(1);
        __syncthreads();

        // -------- mainloop: one barrier per chunk --------
        for (int c = 0; c < NCH; ++c) {
            if (c + 1 < NCH) {
                float* st = smem + ((c + 1) % 3) * STAGE;
                stsA(st); stsB(st + ASZ);
            }
            if (c + 2 < NCH) { ldA(c + 2); ldB(c + 2); }

            const float* As = smem + (c % 3) * STAGE;
            const float* Bs = As + ASZ;
            #pragma unroll
            for (int kb = 0; kb < 4; ++kb) {
                uint32_t a[2][4];
                #pragma unroll
                for (int ml = 0; ml < 2; ++ml) {
                    const float* blk = &As[((w * 2 + ml) * 4 + kb) * 130];
                    float2 p0 = *(const float2*)&blk[2 * lane];        // (a0, a2)
                    float2 p1 = *(const float2*)&blk[2 * lane + 64];   // (a1, a3)
                    a[ml][0] = __float_as_uint(p0.x);
                    a[ml][1] = __float_as_uint(p1.x);
                    a[ml][2] = __float_as_uint(p0.y);
                    a[ml][3] = __float_as_uint(p1.y);
                }
                #pragma unroll
                for (int nb = 0; nb < 6; ++nb) {
                    const float* bb = &Bs[(nb * 4 + kb) * 66];
                    float2 pb = *(const float2*)&bb[2 * lane];         // (b0, b1)
                    uint32_t b0 = __float_as_uint(pb.x);
                    uint32_t b1 = __float_as_uint(pb.y);
                    mma8(acc[0][nb], a[0], b0, b1);
                    mma8(acc[1][nb], a[1], b0, b1);
                }
            }
            __syncthreads();
        }

        // -------- epilogue --------
        int nlim = cnt - tbase; if (nlim > 48) nlim = 48;
        #pragma unroll
        for (int ml = 0; ml < 2; ++ml) {
            const int r0 = mbase + (w * 2 + ml) * 16 + g;
            const int r1 = r0 + 8;
            #pragma unroll
            for (int nb = 0; nb < 6; ++nb) {
                const int n0 = nb * 8 + tg * 2;
                const float* c4 = acc[ml][nb];
                if (PHASE == 1) {
                    size_t b0 = (size_t)r0 * HB_STRIDE + poff + tbase + n0;
                    size_t b1 = (size_t)r1 * HB_STRIDE + poff + tbase + n0;
                    if (n0 + 1 < nlim) {
                        *(float2*)&g_hbufT[b0] = make_float2(gelu_exact(c4[0]), gelu_exact(c4[1]));
                        *(float2*)&g_hbufT[b1] = make_float2(gelu_exact(c4[2]), gelu_exact(c4[3]));
                    } else if (n0 < nlim) {
                        g_hbufT[b0] = gelu_exact(c4[0]);
                        g_hbufT[b1] = gelu_exact(c4[2]);
                    }
                } else {
                    const int t0 = toff + tbase + n0;
                    if (n0 < nlim) {
                        outp[(size_t)t0 * H_N + r0] = c4[0];
                        outp[(size_t)t0 * H_N + r1] = c4[2];
                    }
                    if (n0 + 1 < nlim) {
                        outp[(size_t)(t0 + 1) * H_N + r0] = c4[1];
                        outp[(size_t)(t0 + 1) * H_N + r1] = c4[3];
                    }
                }
            }
        }
        __syncthreads();  // smem reuse across token tiles
    }
}

// ---------------------------------------------------------------------------
// Inputs: d_in[0]=x [T,H] f32, d_in[1]=w1 [E,F,H] f32, d_in[2]=w2 [E,F,H] f32,
//         d_in[3]=tokens_per_expert [E] i32.  d_out=[T,H] f32.
// ---------------------------------------------------------------------------
extern "C" void kernel_launch(void* const* d_in, const int* in_sizes, int n_in,
                              void* d_out, int out_size) {
    const float* x      = (const float*)d_in[0];
    const float* w1     = (const float*)d_in[1];
    const float* w2     = (const float*)d_in[2];
    const int*   counts = (const int*)d_in[3];
    float* out = (float*)d_out;

    cudaFuncSetAttribute(mlp_kernel<1>, cudaFuncAttributeMaxDynamicSharedMemorySize, SMEM_BYTES);
    cudaFuncSetAttribute(mlp_kernel<2>, cudaFuncAttributeMaxDynamicSharedMemorySize, SMEM_BYTES);

    scan_kernel<<<1, 32>>>(counts);
    mlp_kernel<1><<<dim3(F_N / 128, E_N), 128, SMEM_BYTES>>>(x, w1, nullptr);
    mlp_kernel<2><<<dim3(H_N / 128, E_N), 128, SMEM_BYTES>>>(x, w2, out);
}

// round 6
// speedup vs baseline: 4.2782x; 1.2528x over previous
#include <cuda_runtime.h>
#include <cuda_fp16.h>
#include <math.h>
#include <stdint.h>

#define E_N 64
#define H_N 512
#define F_N 2048
#define HB_STRIDE 3072   // padded token columns across all experts

// Scratch (device globals; zero-initialized at module load).
__device__ int g_offs[E_N + 1];    // real token prefix
__device__ int g_poffs[E_N + 1];   // 16-aligned prefix for hbufT columns
__device__ float g_hbufT[(size_t)F_N * HB_STRIDE];  // [f][padded token], 24 MB

__global__ void scan_kernel(const int* __restrict__ counts) {
    if (threadIdx.x == 0) {
        int s = 0, p = 0;
        for (int e = 0; e < E_N; ++e) {
            g_offs[e] = s; g_poffs[e] = p;
            s += counts[e];
            p += (counts[e] + 15) & ~15;
        }
        g_offs[E_N] = s; g_poffs[E_N] = p;
    }
}

__device__ __forceinline__ float gelu_exact(float v) {
    return 0.5f * v * (1.0f + erff(v * 0.70710678118654752f));
}
// Pack two fp32 into half2: result.lo = a, result.hi = b.
__device__ __forceinline__ uint32_t pack2(float a, float b) {
    uint32_t u;
    asm("cvt.rn.f16x2.f32 %0, %1, %2;" : "=r"(u) : "f"(b), "f"(a));
    return u;
}
__device__ __forceinline__ void mma16(float c[4], uint32_t a0, uint32_t a1,
                                      uint32_t a2, uint32_t a3,
                                      uint32_t b0, uint32_t b1) {
    asm volatile(
        "mma.sync.aligned.m16n8k16.row.col.f32.f16.f16.f32 "
        "{%0,%1,%2,%3},{%4,%5,%6,%7},{%8,%9},{%0,%1,%2,%3};"
        : "+f"(c[0]), "+f"(c[1]), "+f"(c[2]), "+f"(c[3])
        : "r"(a0), "r"(a1), "r"(a2), "r"(a3), "r"(b0), "r"(b1));
}

// ---------------------------------------------------------------------------
// Fragment-pair SMEM layout (uint32 = half2 of adjacent k):
// per (16-row m-block x 16-k kb): u32 (row, kpair p) at row*8 + (p&3)*2 + (p>>2)
// -> lane (g,tg) fragment (p=tg, p=tg+4) is one aligned LDS.64 at 2*lane.
// Buffers (BK=32 -> 2 kb per chunk):
//   As[3][8 mb][2 kb][130 u32], Bs[3][6 nb][2 kb][66 u32]
// Schedule: one __syncthreads per chunk, triple buffer:
//   iter c: STS(c+1); LDG(c+2); MMA(c); bar;
// PHASE 1: D[f(128), t(48)] = w1-tile x x-tile, K=512; gelu -> g_hbufT (f32).
// PHASE 2: D[h(128), t(48)] = w2-tile (transposed) x hbufT-tile, K=2048 -> out.
// MMA n-blocks beyond ceil(valid_tokens/8) are skipped (warp-uniform).
// ---------------------------------------------------------------------------
#define ASZ (8 * 2 * 130)   // u32 per A stage (2080)
#define BSZ (6 * 2 * 66)    // u32 per B stage (792)
#define STAGE (ASZ + BSZ)   // 2872 u32 = 11488 B
#define SMEM_BYTES (3 * STAGE * 4)

template <int PHASE>
__global__ void __launch_bounds__(128)
mlp_kernel(const float* __restrict__ x, const float* __restrict__ wgt,
           float* __restrict__ outp) {
    constexpr int KTOT = (PHASE == 1) ? H_N : F_N;
    constexpr int NCH  = KTOT / 32;

    extern __shared__ uint32_t smem[];

    const int tid  = threadIdx.x;
    const int w    = tid >> 5, lane = tid & 31;
    const int g    = lane >> 2, tg = lane & 3;
    const int e     = blockIdx.y;
    const int mbase = blockIdx.x * 128;
    const int toff  = g_offs[e];
    const int cnt   = g_offs[e + 1] - toff;
    const int poff  = g_poffs[e];
    const float* we = wgt + (size_t)e * F_N * H_N;

    float4 rA[8];
    float4 rB[4];

    for (int tbase = 0; tbase < cnt; tbase += 48) {
        const int nlim = (cnt - tbase < 48) ? (cnt - tbase) : 48;
        const int nbl  = (nlim + 7) >> 3;   // active 8-token n-blocks (1..6)

        // ---------------- loaders: gmem -> regs ----------------
        auto ldA = [&](int c) {
            const int k0 = c * 32;
            if (PHASE == 1) {
                #pragma unroll
                for (int i = 0; i < 8; ++i) {
                    int q = tid + i * 128;
                    int m = q >> 3, k4 = q & 7;   // float4 along k
                    rA[i] = *(const float4*)&we[(size_t)(mbase + m) * H_N + k0 + k4 * 4];
                }
            } else {
                #pragma unroll
                for (int i = 0; i < 4; ++i) {     // slot: (kp, m4): 2 LDG.128 (rows k, k+1)
                    int q = tid + i * 128;
                    int m4 = q & 31, kp = q >> 5; // kp 0..15
                    const float* p0 = &we[(size_t)(k0 + 2 * kp) * H_N + mbase + m4 * 4];
                    rA[2 * i]     = *(const float4*)p0;
                    rA[2 * i + 1] = *(const float4*)(p0 + H_N);
                }
            }
        };
        auto ldB = [&](int c) {
            const int k0 = c * 32;
            if (PHASE == 1) {
                #pragma unroll
                for (int i = 0; i < 3; ++i) {     // 48 t x 8 k4 = 384 slots = 3*128
                    int q = tid + i * 128;
                    int t = q >> 3, k4 = q & 7;
                    if (tbase + t < cnt)
                        rB[i] = *(const float4*)&x[(size_t)(toff + tbase + t) * H_N + k0 + k4 * 4];
                    else
                        rB[i] = make_float4(0.f, 0.f, 0.f, 0.f);
                }
            } else {
                #pragma unroll
                for (int i = 0; i < 2; ++i) {     // slot: (kp, n4): 12 n4 x 16 kp = 192
                    int q = tid + i * 128;
                    if (q < 192) {
                        int n4 = q % 12, kp = q / 12;
                        const float* p0 = &g_hbufT[(size_t)(k0 + 2 * kp) * HB_STRIDE +
                                                   poff + tbase + n4 * 4];
                        rB[2 * i]     = *(const float4*)p0;                // row f (k even)
                        rB[2 * i + 1] = *(const float4*)(p0 + HB_STRIDE);  // row f+1
                    }
                }
            }
        };
        // u32 address within a tile: m-block, kb, row, kpair-in-kb
        auto aidx = [](int m, int p) {   // p: kpair 0..15 within chunk
            int pb = p & 7;
            return ((m >> 4) * 2 + (p >> 3)) * 130 + (m & 15) * 8 + (pb & 3) * 2 + (pb >> 2);
        };
        auto bidx = [](int n, int p) {
            int pb = p & 7;
            return ((n >> 3) * 2 + (p >> 3)) * 66 + (n & 7) * 8 + (pb & 3) * 2 + (pb >> 2);
        };
        // ---------------- stores: regs -> packed half2 smem ----------------
        auto stsA = [&](uint32_t* As) {
            if (PHASE == 1) {
                #pragma unroll
                for (int i = 0; i < 8; ++i) {
                    int q = tid + i * 128;
                    int m = q >> 3, k4 = q & 7;
                    As[aidx(m, 2 * k4)]     = pack2(rA[i].x, rA[i].y);
                    As[aidx(m, 2 * k4 + 1)] = pack2(rA[i].z, rA[i].w);
                }
            } else {
                #pragma unroll
                for (int i = 0; i < 4; ++i) {
                    int q = tid + i * 128;
                    int m4 = q & 31, kp = q >> 5;
                    const float* a = (const float*)&rA[2 * i];
                    const float* b = (const float*)&rA[2 * i + 1];
                    #pragma unroll
                    for (int j = 0; j < 4; ++j)
                        As[aidx(m4 * 4 + j, kp)] = pack2(a[j], b[j]);
                }
            }
        };
        auto stsB = [&](uint32_t* Bs) {
            if (PHASE == 1) {
                #pragma unroll
                for (int i = 0; i < 3; ++i) {
                    int q = tid + i * 128;
                    int t = q >> 3, k4 = q & 7;
                    Bs[bidx(t, 2 * k4)]     = pack2(rB[i].x, rB[i].y);
                    Bs[bidx(t, 2 * k4 + 1)] = pack2(rB[i].z, rB[i].w);
                }
            } else {
                #pragma unroll
                for (int i = 0; i < 2; ++i) {
                    int q = tid + i * 128;
                    if (q < 192) {
                        int n4 = q % 12, kp = q / 12;
                        const float* a = (const float*)&rB[2 * i];
                        const float* b = (const float*)&rB[2 * i + 1];
                        #pragma unroll
                        for (int j = 0; j < 4; ++j)
                            Bs[bidx(n4 * 4 + j, kp)] = pack2(a[j], b[j]);
                    }
                }
            }
        };

        float acc[2][6][4];
        #pragma unroll
        for (int ml = 0; ml < 2; ++ml)
            #pragma unroll
            for (int nb = 0; nb < 6; ++nb)
                #pragma unroll
                for (int r = 0; r < 4; ++r) acc[ml][nb][r] = 0.f;

        // -------- prime --------
        ldA(0); ldB(0);
        stsA(smem); stsB(smem + ASZ);
        ldA(1); ldB(1);
        __syncthreads();

        // -------- mainloop --------
        for (int c = 0; c < NCH; ++c) {
            if (c + 1 < NCH) {
                uint32_t* st = smem + ((c + 1) % 3) * STAGE;
                stsA(st); stsB(st + ASZ);
            }
            if (c + 2 < NCH) { ldA(c + 2); ldB(c + 2); }

            const uint32_t* As = smem + (c % 3) * STAGE;
            const uint32_t* Bs = As + ASZ;
            #pragma unroll
            for (int kb = 0; kb < 2; ++kb) {
                uint2 alo[2], ahi[2];
                #pragma unroll
                for (int ml = 0; ml < 2; ++ml) {
                    const uint32_t* blk = &As[((w * 2 + ml) * 2 + kb) * 130];
                    alo[ml] = *(const uint2*)&blk[2 * lane];        // (a0, a2): row g
                    ahi[ml] = *(const uint2*)&blk[2 * lane + 64];   // (a1, a3): row g+8
                }
                #pragma unroll
                for (int nb = 0; nb < 6; ++nb) {
                    if (nb < nbl) {
                        const uint32_t* bb = &Bs[(nb * 2 + kb) * 66];
                        uint2 pb = *(const uint2*)&bb[2 * lane];    // (b0, b1)
                        mma16(acc[0][nb], alo[0].x, ahi[0].x, alo[0].y, ahi[0].y, pb.x, pb.y);
                        mma16(acc[1][nb], alo[1].x, ahi[1].x, alo[1].y, ahi[1].y, pb.x, pb.y);
                    }
                }
            }
            __syncthreads();
        }

        // -------- epilogue --------
        #pragma unroll
        for (int ml = 0; ml < 2; ++ml) {
            const int r0 = mbase + (w * 2 + ml) * 16 + g;
            const int r1 = r0 + 8;
            #pragma unroll
            for (int nb = 0; nb < 6; ++nb) {
                const int n0 = nb * 8 + tg * 2;
                const float* c4 = acc[ml][nb];
                if (PHASE == 1) {
                    size_t b0 = (size_t)r0 * HB_STRIDE + poff + tbase + n0;
                    size_t b1 = (size_t)r1 * HB_STRIDE + poff + tbase + n0;
                    if (n0 + 1 < nlim) {
                        *(float2*)&g_hbufT[b0] = make_float2(gelu_exact(c4[0]), gelu_exact(c4[1]));
                        *(float2*)&g_hbufT[b1] = make_float2(gelu_exact(c4[2]), gelu_exact(c4[3]));
                    } else if (n0 < nlim) {
                        g_hbufT[b0] = gelu_exact(c4[0]);
                        g_hbufT[b1] = gelu_exact(c4[2]);
                    }
                } else {
                    const int t0 = toff + tbase + n0;
                    if (n0 < nlim) {
                        outp[(size_t)t0 * H_N + r0] = c4[0];
                        outp[(size_t)t0 * H_N + r1] = c4[2];
                    }
                    if (n0 + 1 < nlim) {
                        outp[(size_t)(t0 + 1) * H_N + r0] = c4[1];
                        outp[(size_t)(t0 + 1) * H_N + r1] = c4[3];
                    }
                }
            }
        }
        __syncthreads();  // smem reuse across token tiles
    }
}

// ---------------------------------------------------------------------------
// Inputs: d_in[0]=x [T,H] f32, d_in[1]=w1 [E,F,H] f32, d_in[2]=w2 [E,F,H] f32,
//         d_in[3]=tokens_per_expert [E] i32.  d_out=[T,H] f32.
// ---------------------------------------------------------------------------
extern "C" void kernel_launch(void* const* d_in, const int* in_sizes, int n_in,
                              void* d_out, int out_size) {
    const float* x      = (const float*)d_in[0];
    const float* w1     = (const float*)d_in[1];
    const float* w2     = (const float*)d_in[2];
    const int*   counts = (const int*)d_in[3];
    float* out = (float*)d_out;

    cudaFuncSetAttribute(mlp_kernel<1>, cudaFuncAttributeMaxDynamicSharedMemorySize, SMEM_BYTES);
    cudaFuncSetAttribute(mlp_kernel<2>, cudaFuncAttributeMaxDynamicSharedMemorySize, SMEM_BYTES);

    scan_kernel<<<1, 32>>>(counts);
    mlp_kernel<1><<<dim3(F_N / 128, E_N), 128, SMEM_BYTES>>>(x, w1, nullptr);
    mlp_kernel<2><<<dim3(H_N / 128, E_N), 128, SMEM_BYTES>>>(x, w2, out);
}